// round 2
// baseline (speedup 1.0000x reference)
#include <cuda_runtime.h>
#include <math.h>

#define NC   19
#define DD   256
#define HW   16384
#define PX   128
#define NTILE 1024
#define NBLK 152
#define TPB  512
#define TS   257   // padded tile row stride (floats)

// -------- device scratch --------
__device__ float g_PS[NBLK * NC * DD];
__device__ float g_PN[NBLK * NC * DD];
__device__ float g_PC[NBLK * NC];

// smem word layout:
// tile 32896 | acc 4*4864 | nh4 512 | cntb 20 | lab 128 | starts 20 | wcnt 76 | ord2 256(int2)
#define SMEM_WORDS (PX*TS + 4*NC*DD + 512 + 20 + PX + 20 + 4*NC + 2 + 2*PX)
#define SMEM_BYTES (SMEM_WORDS * 4)

__global__ __launch_bounds__(TPB, 1)
void fse_pass1(const float* __restrict__ in, const int* __restrict__ tgt)
{
    extern __shared__ float sm[];
    float* tile  = sm;                    // PX*TS
    float* accS0 = tile + PX * TS;        // NC*DD
    float* accN0 = accS0 + NC * DD;
    float* accS1 = accN0 + NC * DD;
    float* accN1 = accS1 + NC * DD;
    float* nh4   = accN1 + NC * DD;       // 512
    float* cntb  = nh4 + 512;             // 20
    int*   lab    = (int*)(cntb + 20);    // 128
    int*   starts = lab + PX;             // 20
    int*   wcnt   = starts + 20;          // 4*NC = 76
    int2*  ord2   = (int2*)(wcnt + 76 + 2); // 128 int2 (8B aligned by construction)

    const int tid  = threadIdx.x;
    const int lane = tid & 31;
    const int wrp  = tid >> 5;            // 0..15
    const int half = tid >> 8;            // 0/1
    const int dd   = tid & 255;

    for (int i = tid; i < NC * DD; i += TPB) {
        accS0[i] = 0.f; accN0[i] = 0.f; accS1[i] = 0.f; accN1[i] = 0.f;
    }
    if (tid < NC) cntb[tid] = 0.f;
    __syncthreads();

    for (int t = blockIdx.x; t < NTILE; t += NBLK) {
        __syncthreads();   // tile reuse fence (prev accumulate done)
        const int b   = t >> 7;
        const int hw0 = (t & 127) << 7;
        const float* src = in + (size_t)b * DD * HW + hw0;

        int myLab = 0;
        if (tid < PX) { myLab = tgt[b * HW + hw0 + tid]; lab[tid] = myLab; }
        if (tid >= 128 && tid < 128 + 4 * NC) wcnt[tid - 128] = 0;

        // ---- stage: warp covers 16 d-rows, coalesced LDG, conflict-free STS ----
        #pragma unroll 4
        for (int it = 0; it < 16; ++it) {
            const int d = (wrp << 4) + it;
            const float* row = src + (size_t)d * HW;
            float v0 = row[lane], v1 = row[lane + 32], v2 = row[lane + 64], v3 = row[lane + 96];
            float* tb = tile + d;
            tb[(lane      ) * TS] = v0;
            tb[(lane + 32 ) * TS] = v1;
            tb[(lane + 64 ) * TS] = v2;
            tb[(lane + 96 ) * TS] = v3;
        }
        __syncthreads();

        // ---- norm partials: 4 threads per pixel ----
        {
            const int p = tid & 127, h = tid >> 7;
            const float* rp = tile + p * TS + (h << 6);
            float s0 = 0.f, s1 = 0.f;
            #pragma unroll 8
            for (int i = 0; i < 64; i += 2) { float a = rp[i], c = rp[i + 1]; s0 += a * a; s1 += c * c; }
            nh4[(h << 7) + p] = s0 + s1;
        }
        // ---- ballot ranks + per-warp class histogram (warps 0-3) ----
        int myRank = 0;
        if (tid < PX) {
            unsigned m  = __match_any_sync(0xffffffffu, myLab);
            unsigned lt = m & ((1u << lane) - 1u);
            myRank = __popc(lt);
            if (lt == 0u) wcnt[wrp * NC + myLab] = __popc(m);   // leader
        }
        __syncthreads();

        float myR = 0.f;
        if (tid < PX) myR = rsqrtf(nh4[tid] + nh4[128 + tid] + nh4[256 + tid] + nh4[384 + tid]);
        if (tid == 0) {
            int acc = 0;
            #pragma unroll
            for (int c = 0; c < NC; ++c) {
                int ct = wcnt[c] + wcnt[NC + c] + wcnt[2 * NC + c] + wcnt[3 * NC + c];
                starts[c] = acc; acc += ct;
                cntb[c] += (float)ct;
            }
        }
        __syncthreads();

        // ---- scatter class-sorted order entries: {p | cls<<8, rinv} ----
        if (tid < PX) {
            int woff = 0;
            if (wrp > 0) woff += wcnt[myLab];
            if (wrp > 1) woff += wcnt[NC + myLab];
            if (wrp > 2) woff += wcnt[2 * NC + myLab];
            const int pos = starts[myLab] + woff + myRank;
            ord2[pos] = make_int2(tid | (myLab << 8), __float_as_int(myR));
        }
        __syncthreads();

        // ---- accumulate: flat 64-iter walk, run-length flush, reg accumulators ----
        {
            float* aS = half ? accS1 : accS0;
            float* aN = half ? accN1 : accN0;
            int ccur = -1; float sS = 0.f, sN = 0.f;
            const int k0 = half << 6;
            #pragma unroll 4
            for (int k = k0; k < k0 + 64; ++k) {
                const int2 e = ord2[k];
                const int   p   = e.x & 255;
                const int   cls = e.x >> 8;
                const float r   = __int_as_float(e.y);
                const float v   = tile[p * TS + dd];
                if (cls != ccur) {
                    if (ccur >= 0) { aS[ccur * DD + dd] += sS; aN[ccur * DD + dd] += sN; }
                    ccur = cls; sS = 0.f; sN = 0.f;
                }
                sS += v; sN += v * r;
            }
            aS[ccur * DD + dd] += sS; aN[ccur * DD + dd] += sN;
        }
    }
    __syncthreads();

    const size_t base = (size_t)blockIdx.x * NC * DD;
    for (int i = tid; i < NC * DD; i += TPB) {
        g_PS[base + i] = accS0[i] + accS1[i];
        g_PN[base + i] = accN0[i] + accN1[i];
    }
    if (tid < NC) g_PC[blockIdx.x * NC + tid] = cntb[tid];
}

// ---- fused reduction + final loss (single block) ----
__global__ __launch_bounds__(1024)
void fse_final(float* __restrict__ out)
{
    __shared__ float cen[NC * DD];
    __shared__ float nsm[NC * DD];
    __shared__ float cnt_s[NC];
    __shared__ float ncn[NC], nsd[NC];
    __shared__ float pp[NC * NC];
    __shared__ float pl[NC];
    const int tid = threadIdx.x;

    for (int j = tid; j < NC * DD; j += 1024) {
        float sS = 0.f, sN = 0.f;
        #pragma unroll 4
        for (int b = 0; b < NBLK; ++b) {
            sS += g_PS[(size_t)b * NC * DD + j];
            sN += g_PN[(size_t)b * NC * DD + j];
        }
        cen[j] = sS; nsm[j] = sN;
    }
    if (tid < NC) {
        float c = 0.f;
        for (int b = 0; b < NBLK; ++b) c += g_PC[b * NC + tid];
        cnt_s[tid] = c;
    }
    __syncthreads();
    for (int j = tid; j < NC * DD; j += 1024) cen[j] /= fmaxf(cnt_s[j >> 8], 1.f);
    __syncthreads();
    if (tid < NC * 32) {  // one warp per class
        const int c = tid >> 5, ln = tid & 31;
        float n2 = 0.f, dt = 0.f;
        for (int d = ln; d < DD; d += 32) {
            const float cv = cen[c * DD + d];
            n2 += cv * cv;
            dt += cv * nsm[c * DD + d];
        }
        #pragma unroll
        for (int o = 16; o; o >>= 1) {
            n2 += __shfl_down_sync(0xffffffffu, n2, o);
            dt += __shfl_down_sync(0xffffffffu, dt, o);
        }
        if (ln == 0) { ncn[c] = sqrtf(n2); nsd[c] = dt; }
    }
    __syncthreads();
    if (tid < NC * NC) {
        const int i = tid / NC, j = tid - i * NC;
        float g = 0.f;
        for (int d = 0; d < DD; ++d) g += cen[i * DD + d] * cen[j * DD + d];
        const float S = g / fmaxf(ncn[i] * ncn[j], 1e-8f);
        pp[tid] = (i == j) ? (1.f - S) : fmaxf(S, 0.f);
    }
    __syncthreads();
    if (tid < NC) {
        float v = 0.f;
        if (cnt_s[tid] > 0.f) {
            float m = 0.f;
            for (int j = 0; j < NC; ++j) m += pp[tid * NC + j];
            v = m / (float)NC + 1.f - nsd[tid] / (ncn[tid] * cnt_s[tid]);
        }
        pl[tid] = v;
    }
    __syncthreads();
    if (tid == 0) {
        float tot = 0.f;
        for (int i = 0; i < NC; ++i) tot += pl[i];
        out[0] = tot;
    }
}

extern "C" void kernel_launch(void* const* d_in, const int* in_sizes, int n_in,
                              void* d_out, int out_size)
{
    const float* in  = (const float*)d_in[0];
    const int*   tgt = (const int*)d_in[1];
    float*       out = (float*)d_out;

    cudaFuncSetAttribute(fse_pass1, cudaFuncAttributeMaxDynamicSharedMemorySize, SMEM_BYTES);
    fse_pass1<<<NBLK, TPB, SMEM_BYTES>>>(in, tgt);
    fse_final<<<1, 1024>>>(out);
}

// round 3
// speedup vs baseline: 1.3340x; 1.3340x over previous
#include <cuda_runtime.h>
#include <math.h>

#define NC    19
#define DD    256
#define HW    16384
#define PX    64            // pixels per tile
#define NTILE 2048          // 8*HW/PX
#define NBLK  304           // 2 blocks per SM
#define TPB   256
#define TS    257           // padded tile row stride (floats)

// -------- device scratch --------
__device__ float g_PS[NBLK * NC * DD];
__device__ float g_PN[NBLK * NC * DD];
__device__ float g_PC[NBLK * NC];
__device__ float g_sums[NC * DD];
__device__ float g_nsums[NC * DD];
__device__ float g_cnt[NC];

// smem words: tile 64*257 | accS 4864 | accN 4864 | nh4 256 | cntb 20 |
//             lab 64 | starts 20 | wcnt 38 | pad 2 | ord2 128 (int2 -> 8B aligned)
#define SMEM_WORDS (PX*TS + 2*NC*DD + 256 + 20 + PX + 20 + 2*NC + 2 + 2*PX)
#define SMEM_BYTES (SMEM_WORDS * 4)

__global__ __launch_bounds__(TPB, 2)
void fse_pass1(const float* __restrict__ in, const int* __restrict__ tgt)
{
    extern __shared__ float sm[];
    float* tile   = sm;                        // PX*TS
    float* accS   = tile + PX * TS;            // NC*DD
    float* accN   = accS + NC * DD;            // NC*DD
    float* nh4    = accN + NC * DD;            // 256
    float* cntb   = nh4 + 256;                 // 20
    int*   lab    = (int*)(cntb + 20);         // 64
    int*   starts = lab + PX;                  // 20
    int*   wcnt   = starts + 20;               // 2*NC = 38
    int2*  ord2   = (int2*)(wcnt + 38 + 2);    // 64 int2

    const int tid  = threadIdx.x;
    const int lane = tid & 31;
    const int wrp  = tid >> 5;                 // 0..7

    for (int i = tid; i < NC * DD; i += TPB) { accS[i] = 0.f; accN[i] = 0.f; }
    if (tid < NC) cntb[tid] = 0.f;
    __syncthreads();

    for (int t = blockIdx.x; t < NTILE; t += NBLK) {
        __syncthreads();                       // prev accumulate done (tile/ord reuse)
        const int b   = t >> 8;                // 256 tiles per image
        const int hw0 = (t & 255) << 6;
        const float* src = in + (size_t)b * DD * HW + hw0;

        int myLab = 0;
        if (tid < PX) { myLab = tgt[b * HW + hw0 + tid]; lab[tid] = myLab; }
        if (tid >= 64 && tid < 64 + 2 * NC) wcnt[tid - 64] = 0;

        // ---- stage: warp w covers d-rows [32w, 32w+32), 64 px each, coalesced ----
        #pragma unroll
        for (int it = 0; it < 32; ++it) {
            const int d = (wrp << 5) + it;
            const float* row = src + (size_t)d * HW;
            float v0 = row[lane];
            float v1 = row[lane + 32];
            float* tb = tile + d;
            tb[(lane     ) * TS] = v0;
            tb[(lane + 32) * TS] = v1;
        }
        __syncthreads();

        // ---- per-pixel ||feat||^2 partials: 4 threads per pixel ----
        {
            const int p = tid & 63, h = tid >> 6;
            const float* rp = tile + p * TS + (h << 6);
            float s0 = 0.f, s1 = 0.f;
            #pragma unroll 8
            for (int i = 0; i < 64; i += 2) { float a = rp[i], c = rp[i + 1]; s0 += a * a; s1 += c * c; }
            nh4[(h << 6) + p] = s0 + s1;
        }
        // ---- ballot ranks + per-warp class histogram (warps 0-1) ----
        int myRank = 0;
        if (tid < PX) {
            unsigned m  = __match_any_sync(0xffffffffu, myLab);
            unsigned lt = m & ((1u << lane) - 1u);
            myRank = __popc(lt);
            if (lt == 0u) wcnt[wrp * NC + myLab] = __popc(m);
        }
        __syncthreads();

        float myR = 0.f;
        if (tid < PX) myR = rsqrtf(nh4[tid] + nh4[64 + tid] + nh4[128 + tid] + nh4[192 + tid]);
        if (tid == 0) {
            int acc = 0;
            #pragma unroll
            for (int c = 0; c < NC; ++c) {
                const int ct = wcnt[c] + wcnt[NC + c];
                starts[c] = acc; acc += ct;
                cntb[c] += (float)ct;
            }
        }
        __syncthreads();

        // ---- scatter class-sorted order: {p | cls<<8, rinv} ----
        if (tid < PX) {
            const int woff = (wrp > 0) ? wcnt[myLab] : 0;
            ord2[starts[myLab] + woff + myRank] =
                make_int2(tid | (myLab << 8), __float_as_int(myR));
        }
        __syncthreads();

        // ---- accumulate: flat 64-entry walk, run-length flush, reg accumulators ----
        {
            int ccur = -1; float sS = 0.f, sN = 0.f;
            #pragma unroll 4
            for (int k = 0; k < PX; ++k) {
                const int2 e = ord2[k];
                const int   p   = e.x & 255;
                const int   cls = e.x >> 8;
                const float r   = __int_as_float(e.y);
                const float v   = tile[p * TS + tid];
                if (cls != ccur) {
                    if (ccur >= 0) { accS[ccur * DD + tid] += sS; accN[ccur * DD + tid] += sN; }
                    ccur = cls; sS = 0.f; sN = 0.f;
                }
                sS += v; sN += v * r;
            }
            accS[ccur * DD + tid] += sS; accN[ccur * DD + tid] += sN;
        }
    }
    __syncthreads();

    const size_t base = (size_t)blockIdx.x * NC * DD;
    for (int i = tid; i < NC * DD; i += TPB) {
        g_PS[base + i] = accS[i];
        g_PN[base + i] = accN[i];
    }
    if (tid < NC) g_PC[blockIdx.x * NC + tid] = cntb[tid];
}

// ---- parallel partial reduction: thread-per-element, lane-coalesced ----
__global__ __launch_bounds__(256)
void fse_reduce()
{
    const int j = blockIdx.x * 256 + threadIdx.x;
    if (j < NC * DD) {
        float sS = 0.f, sN = 0.f;
        #pragma unroll 8
        for (int b = 0; b < NBLK; ++b) {
            sS += g_PS[(size_t)b * NC * DD + j];
            sN += g_PN[(size_t)b * NC * DD + j];
        }
        g_sums[j] = sS; g_nsums[j] = sN;
    }
    if (blockIdx.x == 0 && threadIdx.x < NC) {
        float c = 0.f;
        for (int b = 0; b < NBLK; ++b) c += g_PC[b * NC + threadIdx.x];
        g_cnt[threadIdx.x] = c;
    }
}

// ---- tiny final: only NC*DD elements from global ----
__global__ __launch_bounds__(1024)
void fse_final(float* __restrict__ out)
{
    __shared__ float cen[NC * DD];
    __shared__ float cnt_s[NC], ncn[NC], nsd[NC], pl[NC];
    __shared__ float pp[NC * NC];
    const int tid = threadIdx.x;

    if (tid < NC) cnt_s[tid] = g_cnt[tid];
    __syncthreads();
    for (int j = tid; j < NC * DD; j += 1024)
        cen[j] = g_sums[j] / fmaxf(cnt_s[j >> 8], 1.f);
    __syncthreads();
    if (tid < NC * 32) {   // warp per class
        const int c = tid >> 5, ln = tid & 31;
        float n2 = 0.f, dt = 0.f;
        for (int d = ln; d < DD; d += 32) {
            const float cv = cen[c * DD + d];
            n2 += cv * cv;
            dt += cv * g_nsums[c * DD + d];
        }
        #pragma unroll
        for (int o = 16; o; o >>= 1) {
            n2 += __shfl_down_sync(0xffffffffu, n2, o);
            dt += __shfl_down_sync(0xffffffffu, dt, o);
        }
        if (ln == 0) { ncn[c] = sqrtf(n2); nsd[c] = dt; }
    }
    __syncthreads();
    if (tid < NC * NC) {
        const int i = tid / NC, j = tid - i * NC;
        float g = 0.f;
        for (int d = 0; d < DD; ++d) g += cen[i * DD + d] * cen[j * DD + d];
        const float S = g / fmaxf(ncn[i] * ncn[j], 1e-8f);
        pp[tid] = (i == j) ? (1.f - S) : fmaxf(S, 0.f);
    }
    __syncthreads();
    if (tid < NC) {
        float v = 0.f;
        if (cnt_s[tid] > 0.f) {
            float m = 0.f;
            for (int j = 0; j < NC; ++j) m += pp[tid * NC + j];
            v = m / (float)NC + 1.f - nsd[tid] / (ncn[tid] * cnt_s[tid]);
        }
        pl[tid] = v;
    }
    __syncthreads();
    if (tid == 0) {
        float tot = 0.f;
        for (int i = 0; i < NC; ++i) tot += pl[i];
        out[0] = tot;
    }
}

extern "C" void kernel_launch(void* const* d_in, const int* in_sizes, int n_in,
                              void* d_out, int out_size)
{
    const float* in  = (const float*)d_in[0];
    const int*   tgt = (const int*)d_in[1];
    float*       out = (float*)d_out;

    cudaFuncSetAttribute(fse_pass1, cudaFuncAttributeMaxDynamicSharedMemorySize, SMEM_BYTES);
    fse_pass1<<<NBLK, TPB, SMEM_BYTES>>>(in, tgt);
    fse_reduce<<<(NC * DD + 255) / 256, 256>>>();
    fse_final<<<1, 1024>>>(out);
}

// round 11
// speedup vs baseline: 1.4417x; 1.0808x over previous
#include <cuda_runtime.h>
#include <math.h>

#define NC    19
#define DD    256
#define HW    16384
#define PX    64            // pixels per tile
#define NTILE 2048          // 8*HW/PX
#define NBLK  304           // 2 blocks per SM
#define TPB   256
#define TS    257           // padded tile row stride (floats)

// -------- device scratch (16B-aligned for float4 access) --------
__device__ __align__(16) float g_PS[NBLK * NC * DD];
__device__ __align__(16) float g_PN[NBLK * NC * DD];
__device__ __align__(16) float g_PC[NBLK * NC];
__device__ __align__(16) float g_sums[NC * DD];
__device__ __align__(16) float g_nsums[NC * DD];
__device__ __align__(16) float g_cnt[NC];

// smem words: tile 16448 | accS 4864 | accN 4864 | nhp 512 | cntb 20 |
//             starts 20 | wcnt 38 | pad 2 | ord2 128
#define SMEM_WORDS (PX*TS + 2*NC*DD + 512 + 20 + 20 + 2*NC + 2 + 2*PX)
#define SMEM_BYTES (SMEM_WORDS * 4)

__global__ __launch_bounds__(TPB, 2)
void fse_pass1(const float* __restrict__ in, const int* __restrict__ tgt)
{
    extern __shared__ __align__(16) float sm[];
    float* tile   = sm;                        // PX*TS
    float* accS   = tile + PX * TS;            // NC*DD
    float* accN   = accS + NC * DD;            // NC*DD
    float* nhp    = accN + NC * DD;            // 8 warps * 64 px = 512
    float* cntb   = nhp + 512;                 // 20
    int*   starts = (int*)(cntb + 20);         // 20
    int*   wcnt   = starts + 20;               // 2*NC = 38
    int2*  ord2   = (int2*)(wcnt + 38 + 2);    // 64 int2 (8B aligned)

    const int tid  = threadIdx.x;
    const int lane = tid & 31;
    const int wrp  = tid >> 5;                 // 0..7

    for (int i = tid; i < NC * DD; i += TPB) { accS[i] = 0.f; accN[i] = 0.f; }
    if (tid < NC) cntb[tid] = 0.f;
    __syncthreads();

    for (int t = blockIdx.x; t < NTILE; t += NBLK) {
        __syncthreads();                       // prev accumulate done (tile/ord2/wcnt reuse)
        const int b   = t >> 8;                // 256 tiles per image
        const int hw0 = (t & 255) << 6;
        const float* src = in + (size_t)b * DD * HW + hw0;

        int myLab = 0;
        if (tid < PX) myLab = tgt[b * HW + hw0 + tid];
        if (tid >= 64 && tid < 64 + 2 * NC) wcnt[tid - 64] = 0;

        // ---- stage (coalesced LDG, conflict-free STS) + fused norm partials ----
        {
            float s0 = 0.f, s1 = 0.f;
            #pragma unroll
            for (int it = 0; it < 32; ++it) {
                const int d = (wrp << 5) + it;
                const float* row = src + (size_t)d * HW;
                const float v0 = row[lane];
                const float v1 = row[lane + 32];
                float* tb = tile + d;
                tb[(lane     ) * TS] = v0;
                tb[(lane + 32) * TS] = v1;
                s0 += v0 * v0;
                s1 += v1 * v1;
            }
            nhp[(wrp << 6) + lane     ] = s0;
            nhp[(wrp << 6) + lane + 32] = s1;
        }
        __syncthreads();   // orders: staging/nhp AND wcnt zeroing before ballot writes

        // ---- ballot ranks + per-warp class histogram + rinv (warps 0-1) ----
        int   myRank = 0;
        float myR    = 0.f;
        if (tid < PX) {
            unsigned m  = __match_any_sync(0xffffffffu, myLab);
            unsigned lt = m & ((1u << lane) - 1u);
            myRank = __popc(lt);
            if (lt == 0u) wcnt[wrp * NC + myLab] = __popc(m);   // leader
            float n2 = 0.f;
            #pragma unroll
            for (int k = 0; k < 8; ++k) n2 += nhp[(k << 6) + tid];
            myR = rsqrtf(n2);
        }
        __syncthreads();   // wcnt complete before scan

        // ---- warp-0 shfl prefix scan over class counts ----
        if (wrp == 0) {
            int ct = (lane < NC) ? (wcnt[lane] + wcnt[NC + lane]) : 0;
            int incl = ct;
            #pragma unroll
            for (int o = 1; o < 32; o <<= 1) {
                const int nb = __shfl_up_sync(0xffffffffu, incl, o);
                if (lane >= o) incl += nb;
            }
            if (lane < NC) { starts[lane] = incl - ct; cntb[lane] += (float)ct; }
        }
        __syncthreads();   // starts ready before scatter

        // ---- scatter class-sorted order: {p | cls<<8, rinv} ----
        if (tid < PX) {
            const int woff = (wrp > 0) ? wcnt[myLab] : 0;
            ord2[starts[myLab] + woff + myRank] =
                make_int2(tid | (myLab << 8), __float_as_int(myR));
        }
        __syncthreads();   // ord2 ready before accumulate

        // ---- accumulate: flat 64-entry walk, run-length flush, reg accumulators ----
        {
            int ccur = -1; float sS = 0.f, sN = 0.f;
            #pragma unroll 4
            for (int k = 0; k < PX; ++k) {
                const int2 e = ord2[k];
                const int   p   = e.x & 255;
                const int   cls = e.x >> 8;
                const float r   = __int_as_float(e.y);
                const float v   = tile[p * TS + tid];
                if (cls != ccur) {
                    if (ccur >= 0) { accS[ccur * DD + tid] += sS; accN[ccur * DD + tid] += sN; }
                    ccur = cls; sS = 0.f; sN = 0.f;
                }
                sS += v; sN += v * r;
            }
            accS[ccur * DD + tid] += sS; accN[ccur * DD + tid] += sN;
        }
    }
    __syncthreads();

    // ---- vectorized flush of per-block partials ----
    {
        const float4* aS4 = (const float4*)accS;
        const float4* aN4 = (const float4*)accN;
        float4* pS4 = (float4*)(g_PS + (size_t)blockIdx.x * NC * DD);
        float4* pN4 = (float4*)(g_PN + (size_t)blockIdx.x * NC * DD);
        for (int i = tid; i < (NC * DD) / 4; i += TPB) {
            pS4[i] = aS4[i];
            pN4[i] = aN4[i];
        }
    }
    if (tid < NC) g_PC[blockIdx.x * NC + tid] = cntb[tid];
}

// ---- partial reduction: 38 blocks, float4, 4-way deterministic b-split ----
#define NVEC (NC * DD / 4)          // 1216 float4 per array
#define VPB  64                     // vec outputs per block
#define BCH  (NBLK / 4)             // 76 b's per chunk

__global__ __launch_bounds__(256)
void fse_reduce()
{
    __shared__ float4 part[256];
    const int tid = threadIdx.x;
    const bool isN = blockIdx.x >= (NVEC / VPB);
    const int  blk = isN ? (blockIdx.x - NVEC / VPB) : blockIdx.x;
    const float4* src = (const float4*)(isN ? g_PN : g_PS);
    float4* dst = (float4*)(isN ? g_nsums : g_sums);

    const int vec   = blk * VPB + (tid >> 2);
    const int chunk = tid & 3;
    float4 s = make_float4(0.f, 0.f, 0.f, 0.f);
    const int b0 = chunk * BCH;
    #pragma unroll 4
    for (int b = b0; b < b0 + BCH; ++b) {
        const float4 v = src[(size_t)b * NVEC + vec];
        s.x += v.x; s.y += v.y; s.z += v.z; s.w += v.w;
    }
    part[tid] = s;
    __syncthreads();
    if (tid < VPB) {
        const float4 a  = part[tid * 4 + 0];
        const float4 bq = part[tid * 4 + 1];
        const float4 c  = part[tid * 4 + 2];
        const float4 d  = part[tid * 4 + 3];
        dst[blk * VPB + tid] = make_float4(a.x + bq.x + c.x + d.x,
                                           a.y + bq.y + c.y + d.y,
                                           a.z + bq.z + c.z + d.z,
                                           a.w + bq.w + c.w + d.w);
    }
    if (blockIdx.x == 0 && tid < NC) {
        float c = 0.f;
        for (int b = 0; b < NBLK; ++b) c += g_PC[b * NC + tid];
        g_cnt[tid] = c;
    }
}

// ---- tiny final ----
__global__ __launch_bounds__(1024)
void fse_final(float* __restrict__ out)
{
    __shared__ float cen[NC * DD];
    __shared__ float cnt_s[NC], ncn[NC], nsd[NC], pl[NC];
    __shared__ float pp[NC * NC];
    const int tid = threadIdx.x;

    if (tid < NC) cnt_s[tid] = g_cnt[tid];
    __syncthreads();
    for (int j = tid; j < NC * DD; j += 1024)
        cen[j] = g_sums[j] / fmaxf(cnt_s[j >> 8], 1.f);
    __syncthreads();
    if (tid < NC * 32) {   // warp per class
        const int c = tid >> 5, ln = tid & 31;
        float n2 = 0.f, dt = 0.f;
        for (int d = ln; d < DD; d += 32) {
            const float cv = cen[c * DD + d];
            n2 += cv * cv;
            dt += cv * g_nsums[c * DD + d];
        }
        #pragma unroll
        for (int o = 16; o; o >>= 1) {
            n2 += __shfl_down_sync(0xffffffffu, n2, o);
            dt += __shfl_down_sync(0xffffffffu, dt, o);
        }
        if (ln == 0) { ncn[c] = sqrtf(n2); nsd[c] = dt; }
    }
    __syncthreads();
    if (tid < NC * NC) {
        const int i = tid / NC, j = tid - i * NC;
        float g = 0.f;
        for (int d = 0; d < DD; ++d) g += cen[i * DD + d] * cen[j * DD + d];
        const float S = g / fmaxf(ncn[i] * ncn[j], 1e-8f);
        pp[tid] = (i == j) ? (1.f - S) : fmaxf(S, 0.f);
    }
    __syncthreads();
    if (tid < NC) {
        float v = 0.f;
        if (cnt_s[tid] > 0.f) {
            float m = 0.f;
            for (int j = 0; j < NC; ++j) m += pp[tid * NC + j];
            v = m / (float)NC + 1.f - nsd[tid] / (ncn[tid] * cnt_s[tid]);
        }
        pl[tid] = v;
    }
    __syncthreads();
    if (tid == 0) {
        float tot = 0.f;
        for (int i = 0; i < NC; ++i) tot += pl[i];
        out[0] = tot;
    }
}

extern "C" void kernel_launch(void* const* d_in, const int* in_sizes, int n_in,
                              void* d_out, int out_size)
{
    const float* in  = (const float*)d_in[0];
    const int*   tgt = (const int*)d_in[1];
    float*       out = (float*)d_out;

    cudaFuncSetAttribute(fse_pass1, cudaFuncAttributeMaxDynamicSharedMemorySize, SMEM_BYTES);
    fse_pass1<<<NBLK, TPB, SMEM_BYTES>>>(in, tgt);
    fse_reduce<<<2 * (NVEC / VPB), 256>>>();
    fse_final<<<1, 1024>>>(out);
}

// round 12
// speedup vs baseline: 1.4651x; 1.0162x over previous
#include <cuda_runtime.h>
#include <math.h>

#define NC    19
#define DD    256
#define HW    16384
#define PX    64            // pixels per tile
#define NTILE 2048          // 8*HW/PX
#define NBLK  304           // 2 blocks per SM
#define TPB   256
#define TS    257           // padded tile row stride (floats); 257 == 1 mod 32

// -------- device scratch (16B-aligned for float4 access) --------
__device__ __align__(16) float g_PS[NBLK * NC * DD];
__device__ __align__(16) float g_PN[NBLK * NC * DD];
__device__ __align__(16) float g_PC[NBLK * NC];
__device__ __align__(16) float g_sums[NC * DD];
__device__ __align__(16) float g_nsums[NC * DD];
__device__ __align__(16) float g_cnt[NC];
__device__ unsigned int g_ctr = 0;

// smem words: tile 16448 | accS 4864 | accN 4864 | nhp 512 | cntb 20 |
//             starts 20 | wcnt 38 | pad 2 | ord2 128
#define SMEM_WORDS (PX*TS + 2*NC*DD + 512 + 20 + 20 + 2*NC + 2 + 2*PX)
#define SMEM_BYTES (SMEM_WORDS * 4)

__global__ __launch_bounds__(TPB, 2)
void fse_pass1(const float* __restrict__ in, const int* __restrict__ tgt)
{
    extern __shared__ __align__(16) float sm[];
    float* tile   = sm;                        // PX*TS
    float* accS   = tile + PX * TS;            // NC*DD
    float* accN   = accS + NC * DD;            // NC*DD
    float* nhp    = accN + NC * DD;            // 8 warps * 64 px = 512
    float* cntb   = nhp + 512;                 // 20
    int*   starts = (int*)(cntb + 20);         // 20
    int*   wcnt   = starts + 20;               // 2*NC = 38
    int2*  ord2   = (int2*)(wcnt + 38 + 2);    // 64 int2 (8B aligned)

    const int tid  = threadIdx.x;
    const int lane = tid & 31;
    const int wrp  = tid >> 5;                 // 0..7
    const int hi   = lane >> 4;                // 0/1: which of 2 d-rows per iter
    const int px0  = (lane & 15) << 2;         // 4-pixel group

    for (int i = tid; i < NC * DD; i += TPB) { accS[i] = 0.f; accN[i] = 0.f; }
    if (tid < NC) cntb[tid] = 0.f;
    __syncthreads();

    for (int t = blockIdx.x; t < NTILE; t += NBLK) {
        __syncthreads();                       // prev accumulate done (tile/ord2/wcnt reuse)
        const int b   = t >> 8;
        const int hw0 = (t & 255) << 6;
        const float* src = in + (size_t)b * DD * HW + hw0;

        int myLab = 0;
        if (tid < PX) myLab = tgt[b * HW + hw0 + tid];
        if (tid >= 64 && tid < 64 + 2 * NC) wcnt[tid - 64] = 0;

        // ---- stage via LDG.128 (16/thread) + fused norm partials ----
        {
            float s0 = 0.f, s1 = 0.f, s2 = 0.f, s3 = 0.f;
            #pragma unroll
            for (int it = 0; it < 16; ++it) {
                const int d = (wrp << 5) + (it << 1) + hi;
                const float4 v = *(const float4*)(src + (size_t)d * HW + px0);
                float* tb = tile + d;
                tb[(px0    ) * TS] = v.x;
                tb[(px0 + 1) * TS] = v.y;
                tb[(px0 + 2) * TS] = v.z;
                tb[(px0 + 3) * TS] = v.w;
                s0 += v.x * v.x; s1 += v.y * v.y; s2 += v.z * v.z; s3 += v.w * v.w;
            }
            // combine across the two d-halves (lane ^ 16)
            s0 += __shfl_xor_sync(0xffffffffu, s0, 16);
            s1 += __shfl_xor_sync(0xffffffffu, s1, 16);
            s2 += __shfl_xor_sync(0xffffffffu, s2, 16);
            s3 += __shfl_xor_sync(0xffffffffu, s3, 16);
            if (hi == 0)
                *(float4*)(nhp + (wrp << 6) + px0) = make_float4(s0, s1, s2, s3);
        }
        __syncthreads();   // staging/nhp + wcnt zeroing ordered before ballot writes

        // ---- ballot ranks + per-warp class histogram + rinv (warps 0-1) ----
        int   myRank = 0;
        float myR    = 0.f;
        if (tid < PX) {
            unsigned m  = __match_any_sync(0xffffffffu, myLab);
            unsigned lt = m & ((1u << lane) - 1u);
            myRank = __popc(lt);
            if (lt == 0u) wcnt[wrp * NC + myLab] = __popc(m);   // leader
            float n2 = 0.f;
            #pragma unroll
            for (int k = 0; k < 8; ++k) n2 += nhp[(k << 6) + tid];
            myR = rsqrtf(n2);
        }
        __syncthreads();   // wcnt complete before scan

        // ---- warp-0 shfl prefix scan over class counts ----
        if (wrp == 0) {
            int ct = (lane < NC) ? (wcnt[lane] + wcnt[NC + lane]) : 0;
            int incl = ct;
            #pragma unroll
            for (int o = 1; o < 32; o <<= 1) {
                const int nb = __shfl_up_sync(0xffffffffu, incl, o);
                if (lane >= o) incl += nb;
            }
            if (lane < NC) { starts[lane] = incl - ct; cntb[lane] += (float)ct; }
        }
        __syncthreads();   // starts ready before scatter

        // ---- scatter class-sorted order: {p | cls<<8, rinv} ----
        if (tid < PX) {
            const int woff = (wrp > 0) ? wcnt[myLab] : 0;
            ord2[starts[myLab] + woff + myRank] =
                make_int2(tid | (myLab << 8), __float_as_int(myR));
        }
        __syncthreads();   // ord2 ready before accumulate

        // ---- accumulate: flat 64-entry walk, run-length flush ----
        {
            int ccur = -1; float sS = 0.f, sN = 0.f;
            #pragma unroll 4
            for (int k = 0; k < PX; ++k) {
                const int2 e = ord2[k];
                const int   p   = e.x & 255;
                const int   cls = e.x >> 8;
                const float r   = __int_as_float(e.y);
                const float v   = tile[p * TS + tid];
                if (cls != ccur) {
                    if (ccur >= 0) { accS[ccur * DD + tid] += sS; accN[ccur * DD + tid] += sN; }
                    ccur = cls; sS = 0.f; sN = 0.f;
                }
                sS += v; sN += v * r;
            }
            accS[ccur * DD + tid] += sS; accN[ccur * DD + tid] += sN;
        }
    }
    __syncthreads();

    // ---- vectorized flush of per-block partials ----
    {
        const float4* aS4 = (const float4*)accS;
        const float4* aN4 = (const float4*)accN;
        float4* pS4 = (float4*)(g_PS + (size_t)blockIdx.x * NC * DD);
        float4* pN4 = (float4*)(g_PN + (size_t)blockIdx.x * NC * DD);
        for (int i = tid; i < (NC * DD) / 4; i += TPB) {
            pS4[i] = aS4[i];
            pN4[i] = aN4[i];
        }
    }
    if (tid < NC) g_PC[blockIdx.x * NC + tid] = cntb[tid];
}

// ---- fused tail: 152-block reduce, last block computes the loss ----
#define NVEC (NC * DD / 4)          // 1216 float4 per array
#define TGRID 152                   // 152*16 = 2*NVEC vec outputs

__global__ __launch_bounds__(256)
void fse_tail(float* __restrict__ out)
{
    __shared__ float4 part[256];
    __shared__ int s_last;
    __shared__ float cen[NC * DD];
    __shared__ float cnt_s[NC], ncn[NC], nsd[NC], pl[NC];
    __shared__ float pp[NC * NC];

    const int tid = threadIdx.x;
    const int vl  = tid & 15;          // vec within block (coalesced)
    const int sub = tid >> 4;          // 16-way b-split
    const int gv  = blockIdx.x * 16 + vl;
    const bool isN = gv >= NVEC;
    const int  v   = isN ? (gv - NVEC) : gv;
    const float4* src = (const float4*)(isN ? g_PN : g_PS);
    float4* dst = (float4*)(isN ? g_nsums : g_sums);

    float4 s = make_float4(0.f, 0.f, 0.f, 0.f);
    #pragma unroll
    for (int i = 0; i < NBLK / 16; ++i) {       // 19 iters
        const float4 w = src[(size_t)(sub * (NBLK / 16) + i) * NVEC + v];
        s.x += w.x; s.y += w.y; s.z += w.z; s.w += w.w;
    }
    part[tid] = s;
    if (blockIdx.x == 0 && tid < NC) {
        float c = 0.f;
        for (int b = 0; b < NBLK; ++b) c += g_PC[b * NC + tid];
        g_cnt[tid] = c;
    }
    __syncthreads();
    if (tid < 16) {                              // fixed-order deterministic combine
        float4 tot = make_float4(0.f, 0.f, 0.f, 0.f);
        #pragma unroll
        for (int k = 0; k < 16; ++k) {
            const float4 w = part[k * 16 + tid];
            tot.x += w.x; tot.y += w.y; tot.z += w.z; tot.w += w.w;
        }
        dst[v] = tot;                            // (vl == tid here)
    }
    __threadfence();
    __syncthreads();
    if (tid == 0) s_last = (atomicAdd(&g_ctr, 1u) == TGRID - 1) ? 1 : 0;
    __syncthreads();
    if (!s_last) return;
    __threadfence();                             // acquire side

    // ---- final loss (one block, all inputs L2-hot, 39 KB) ----
    if (tid < NC) cnt_s[tid] = g_cnt[tid];
    __syncthreads();
    for (int j = tid; j < NC * DD; j += 256)
        cen[j] = g_sums[j] / fmaxf(cnt_s[j >> 8], 1.f);
    __syncthreads();
    {
        const int wrp = tid >> 5, ln = tid & 31;
        for (int c = wrp; c < NC; c += 8) {
            float n2 = 0.f, dt = 0.f;
            for (int d = ln; d < DD; d += 32) {
                const float cv = cen[c * DD + d];
                n2 += cv * cv;
                dt += cv * g_nsums[c * DD + d];
            }
            #pragma unroll
            for (int o = 16; o; o >>= 1) {
                n2 += __shfl_down_sync(0xffffffffu, n2, o);
                dt += __shfl_down_sync(0xffffffffu, dt, o);
            }
            if (ln == 0) { ncn[c] = sqrtf(n2); nsd[c] = dt; }
        }
    }
    __syncthreads();
    for (int pr = tid; pr < NC * NC; pr += 256) {
        const int i = pr / NC, j = pr - i * NC;
        float g = 0.f;
        for (int d = 0; d < DD; ++d) g += cen[i * DD + d] * cen[j * DD + d];
        const float S = g / fmaxf(ncn[i] * ncn[j], 1e-8f);
        pp[pr] = (i == j) ? (1.f - S) : fmaxf(S, 0.f);
    }
    __syncthreads();
    if (tid < NC) {
        float vv = 0.f;
        if (cnt_s[tid] > 0.f) {
            float m = 0.f;
            for (int j = 0; j < NC; ++j) m += pp[tid * NC + j];
            vv = m / (float)NC + 1.f - nsd[tid] / (ncn[tid] * cnt_s[tid]);
        }
        pl[tid] = vv;
    }
    __syncthreads();
    if (tid == 0) {
        float tot = 0.f;
        for (int i = 0; i < NC; ++i) tot += pl[i];
        out[0] = tot;
        g_ctr = 0;                               // reset for next graph replay
    }
}

extern "C" void kernel_launch(void* const* d_in, const int* in_sizes, int n_in,
                              void* d_out, int out_size)
{
    const float* in  = (const float*)d_in[0];
    const int*   tgt = (const int*)d_in[1];
    float*       out = (float*)d_out;

    cudaFuncSetAttribute(fse_pass1, cudaFuncAttributeMaxDynamicSharedMemorySize, SMEM_BYTES);
    fse_pass1<<<NBLK, TPB, SMEM_BYTES>>>(in, tgt);
    fse_tail<<<TGRID, 256>>>(out);
}

// round 13
// speedup vs baseline: 1.7295x; 1.1805x over previous
#include <cuda_runtime.h>
#include <math.h>

#define NC    19
#define DD    256
#define HW    16384
#define PX    64            // pixels per tile
#define NTILE 2048          // 8*HW/PX
#define NBLK  304           // 2 blocks per SM
#define TPB   256
#define TS    257           // padded tile row stride (floats)

// -------- device scratch (16B-aligned for float4 access) --------
__device__ __align__(16) float g_PS[NBLK * NC * DD];
__device__ __align__(16) float g_PN[NBLK * NC * DD];
__device__ __align__(16) float g_PC[NBLK * NC];
__device__ __align__(16) float g_sums[NC * DD];
__device__ __align__(16) float g_nsums[NC * DD];
__device__ unsigned int g_ctr = 0;

// smem words: tile 16448 | accS 4864 | accN 4864 | nhp 512 | cntb 20 |
//             starts 20 | wcnt 38 | pad 2 | ord2 128
#define SMEM_WORDS (PX*TS + 2*NC*DD + 512 + 20 + 20 + 2*NC + 2 + 2*PX)
#define SMEM_BYTES (SMEM_WORDS * 4)

__global__ __launch_bounds__(TPB, 2)
void fse_pass1(const float* __restrict__ in, const int* __restrict__ tgt)
{
    extern __shared__ __align__(16) float sm[];
    float* tile   = sm;
    float* accS   = tile + PX * TS;
    float* accN   = accS + NC * DD;
    float* nhp    = accN + NC * DD;
    float* cntb   = nhp + 512;
    int*   starts = (int*)(cntb + 20);
    int*   wcnt   = starts + 20;
    int2*  ord2   = (int2*)(wcnt + 38 + 2);

    const int tid  = threadIdx.x;
    const int lane = tid & 31;
    const int wrp  = tid >> 5;
    const int hi   = lane >> 4;
    const int px0  = (lane & 15) << 2;

    for (int i = tid; i < NC * DD; i += TPB) { accS[i] = 0.f; accN[i] = 0.f; }
    if (tid < NC) cntb[tid] = 0.f;
    __syncthreads();

    for (int t = blockIdx.x; t < NTILE; t += NBLK) {
        __syncthreads();
        const int b   = t >> 8;
        const int hw0 = (t & 255) << 6;
        const float* src = in + (size_t)b * DD * HW + hw0;

        int myLab = 0;
        if (tid < PX) myLab = tgt[b * HW + hw0 + tid];
        if (tid >= 64 && tid < 64 + 2 * NC) wcnt[tid - 64] = 0;

        // ---- stage via LDG.128 + fused norm partials ----
        {
            float s0 = 0.f, s1 = 0.f, s2 = 0.f, s3 = 0.f;
            #pragma unroll
            for (int it = 0; it < 16; ++it) {
                const int d = (wrp << 5) + (it << 1) + hi;
                const float4 v = *(const float4*)(src + (size_t)d * HW + px0);
                float* tb = tile + d;
                tb[(px0    ) * TS] = v.x;
                tb[(px0 + 1) * TS] = v.y;
                tb[(px0 + 2) * TS] = v.z;
                tb[(px0 + 3) * TS] = v.w;
                s0 += v.x * v.x; s1 += v.y * v.y; s2 += v.z * v.z; s3 += v.w * v.w;
            }
            s0 += __shfl_xor_sync(0xffffffffu, s0, 16);
            s1 += __shfl_xor_sync(0xffffffffu, s1, 16);
            s2 += __shfl_xor_sync(0xffffffffu, s2, 16);
            s3 += __shfl_xor_sync(0xffffffffu, s3, 16);
            if (hi == 0)
                *(float4*)(nhp + (wrp << 6) + px0) = make_float4(s0, s1, s2, s3);
        }
        __syncthreads();

        // ---- ballot ranks + per-warp class histogram + rinv ----
        int   myRank = 0;
        float myR    = 0.f;
        if (tid < PX) {
            unsigned m  = __match_any_sync(0xffffffffu, myLab);
            unsigned lt = m & ((1u << lane) - 1u);
            myRank = __popc(lt);
            if (lt == 0u) wcnt[wrp * NC + myLab] = __popc(m);
            float n2 = 0.f;
            #pragma unroll
            for (int k = 0; k < 8; ++k) n2 += nhp[(k << 6) + tid];
            myR = rsqrtf(n2);
        }
        __syncthreads();

        // ---- warp-0 shfl prefix scan ----
        if (wrp == 0) {
            int ct = (lane < NC) ? (wcnt[lane] + wcnt[NC + lane]) : 0;
            int incl = ct;
            #pragma unroll
            for (int o = 1; o < 32; o <<= 1) {
                const int nb = __shfl_up_sync(0xffffffffu, incl, o);
                if (lane >= o) incl += nb;
            }
            if (lane < NC) { starts[lane] = incl - ct; cntb[lane] += (float)ct; }
        }
        __syncthreads();

        // ---- scatter class-sorted order ----
        if (tid < PX) {
            const int woff = (wrp > 0) ? wcnt[myLab] : 0;
            ord2[starts[myLab] + woff + myRank] =
                make_int2(tid | (myLab << 8), __float_as_int(myR));
        }
        __syncthreads();

        // ---- accumulate: flat 64-entry walk, run-length flush ----
        {
            int ccur = -1; float sS = 0.f, sN = 0.f;
            #pragma unroll 4
            for (int k = 0; k < PX; ++k) {
                const int2 e = ord2[k];
                const int   p   = e.x & 255;
                const int   cls = e.x >> 8;
                const float r   = __int_as_float(e.y);
                const float v   = tile[p * TS + tid];
                if (cls != ccur) {
                    if (ccur >= 0) { accS[ccur * DD + tid] += sS; accN[ccur * DD + tid] += sN; }
                    ccur = cls; sS = 0.f; sN = 0.f;
                }
                sS += v; sN += v * r;
            }
            accS[ccur * DD + tid] += sS; accN[ccur * DD + tid] += sN;
        }
    }
    __syncthreads();

    {
        const float4* aS4 = (const float4*)accS;
        const float4* aN4 = (const float4*)accN;
        float4* pS4 = (float4*)(g_PS + (size_t)blockIdx.x * NC * DD);
        float4* pN4 = (float4*)(g_PN + (size_t)blockIdx.x * NC * DD);
        for (int i = tid; i < (NC * DD) / 4; i += TPB) {
            pS4[i] = aS4[i];
            pN4[i] = aN4[i];
        }
    }
    if (tid < NC) g_PC[blockIdx.x * NC + tid] = cntb[tid];
}

// ---- fused tail: 152-block reduce, last block computes the loss ----
#define NVEC (NC * DD / 4)          // 1216 float4 per array
#define TGRID 152

__global__ __launch_bounds__(256)
void fse_tail(float* __restrict__ out)
{
    __shared__ float4 part[256];
    __shared__ float pcp[8][NC];
    __shared__ int s_last;
    __shared__ float cen[NC * DD];
    __shared__ float cnt_s[NC], ncn[NC], nsd[NC], pl[NC];
    __shared__ float pp[NC * NC];

    const int tid = threadIdx.x;
    const int vl  = tid & 15;
    const int sub = tid >> 4;                    // 16-way b-split, 19 b's each
    const int gv  = blockIdx.x * 16 + vl;
    const bool isN = gv >= NVEC;
    const int  v   = isN ? (gv - NVEC) : gv;
    const float4* src = (const float4*)(isN ? g_PN : g_PS);
    float4* dst = (float4*)(isN ? g_nsums : g_sums);

    // ---- reduce: batched loads (MLP>=4), fixed order ----
    float4 s = make_float4(0.f, 0.f, 0.f, 0.f);
    {
        const float4* p = src + (size_t)(sub * 19) * NVEC + v;
        #pragma unroll
        for (int base = 0; base < 16; base += 4) {
            float4 w0 = p[(size_t)(base + 0) * NVEC];
            float4 w1 = p[(size_t)(base + 1) * NVEC];
            float4 w2 = p[(size_t)(base + 2) * NVEC];
            float4 w3 = p[(size_t)(base + 3) * NVEC];
            s.x += w0.x + w1.x + w2.x + w3.x;
            s.y += w0.y + w1.y + w2.y + w3.y;
            s.z += w0.z + w1.z + w2.z + w3.z;
            s.w += w0.w + w1.w + w2.w + w3.w;
        }
        float4 w0 = p[(size_t)16 * NVEC];
        float4 w1 = p[(size_t)17 * NVEC];
        float4 w2 = p[(size_t)18 * NVEC];
        s.x += w0.x + w1.x + w2.x;
        s.y += w0.y + w1.y + w2.y;
        s.z += w0.z + w1.z + w2.z;
        s.w += w0.w + w1.w + w2.w;
    }
    part[tid] = s;
    __syncthreads();
    if (tid < 16) {                              // fixed-order deterministic combine
        float4 tot = make_float4(0.f, 0.f, 0.f, 0.f);
        #pragma unroll
        for (int k = 0; k < 16; ++k) {
            const float4 w = part[k * 16 + tid];
            tot.x += w.x; tot.y += w.y; tot.z += w.z; tot.w += w.w;
        }
        dst[v] = tot;
    }
    __threadfence();
    __syncthreads();
    if (tid == 0) s_last = (atomicAdd(&g_ctr, 1u) == TGRID - 1) ? 1 : 0;
    __syncthreads();
    if (!s_last) return;
    __threadfence();                             // acquire side

    // ---- last block: counts (parallel, deterministic fixed-order) ----
    {
        const int grp = tid >> 5, c = tid & 31;
        if (c < NC) {
            float acc = 0.f;
            const int b0 = grp * (NBLK / 8);     // 38 b's per group
            #pragma unroll 2
            for (int b = b0; b < b0 + NBLK / 8; ++b) acc += g_PC[b * NC + c];
            pcp[grp][c] = acc;
        }
    }
    __syncthreads();
    if (tid < NC) {
        float c = 0.f;
        #pragma unroll
        for (int k = 0; k < 8; ++k) c += pcp[k][tid];
        cnt_s[tid] = c;
    }
    __syncthreads();

    // ---- centers ----
    for (int j = tid; j < NC * DD; j += 256)
        cen[j] = g_sums[j] / fmaxf(cnt_s[j >> 8], 1.f);
    __syncthreads();

    // ---- per-class norm + dot(center, nsum): warp per class, lanes over d ----
    {
        const int wrp = tid >> 5, ln = tid & 31;
        for (int c = wrp; c < NC; c += 8) {
            float n2 = 0.f, dt = 0.f;
            #pragma unroll
            for (int k = 0; k < 8; ++k) {
                const int d = ln + (k << 5);
                const float cv = cen[c * DD + d];
                n2 += cv * cv;
                dt += cv * g_nsums[c * DD + d];
            }
            #pragma unroll
            for (int o = 16; o; o >>= 1) {
                n2 += __shfl_down_sync(0xffffffffu, n2, o);
                dt += __shfl_down_sync(0xffffffffu, dt, o);
            }
            if (ln == 0) { ncn[c] = sqrtf(n2); nsd[c] = dt; }
        }
    }
    __syncthreads();

    // ---- Gram matrix: warp per pair, lanes over d (conflict-free) ----
    {
        const int wrp = tid >> 5, ln = tid & 31;
        for (int pr = wrp; pr < NC * NC; pr += 8) {
            const int i = pr / NC, j = pr - i * NC;
            float g = 0.f;
            #pragma unroll
            for (int k = 0; k < 8; ++k) {
                const int d = ln + (k << 5);
                g += cen[i * DD + d] * cen[j * DD + d];
            }
            #pragma unroll
            for (int o = 16; o; o >>= 1) g += __shfl_down_sync(0xffffffffu, g, o);
            if (ln == 0) {
                const float S = g / fmaxf(ncn[i] * ncn[j], 1e-8f);
                pp[pr] = (i == j) ? (1.f - S) : fmaxf(S, 0.f);
            }
        }
    }
    __syncthreads();
    if (tid < NC) {
        float vv = 0.f;
        if (cnt_s[tid] > 0.f) {
            float m = 0.f;
            for (int j = 0; j < NC; ++j) m += pp[tid * NC + j];
            vv = m / (float)NC + 1.f - nsd[tid] / (ncn[tid] * cnt_s[tid]);
        }
        pl[tid] = vv;
    }
    __syncthreads();
    if (tid == 0) {
        float tot = 0.f;
        for (int i = 0; i < NC; ++i) tot += pl[i];
        out[0] = tot;
        g_ctr = 0;                               // reset for next graph replay
    }
}

extern "C" void kernel_launch(void* const* d_in, const int* in_sizes, int n_in,
                              void* d_out, int out_size)
{
    const float* in  = (const float*)d_in[0];
    const int*   tgt = (const int*)d_in[1];
    float*       out = (float*)d_out;

    cudaFuncSetAttribute(fse_pass1, cudaFuncAttributeMaxDynamicSharedMemorySize, SMEM_BYTES);
    fse_pass1<<<NBLK, TPB, SMEM_BYTES>>>(in, tgt);
    fse_tail<<<TGRID, 256>>>(out);
}